// round 4
// baseline (speedup 1.0000x reference)
#include <cuda_runtime.h>

#define N_NODES 50000
#define N_EDGES 800000
#define C_IN    128
#define HEADS   4
#define C_HEAD  32
#define C_OUT   128
#define NEG_SLOPE 0.2f

// ---------------- scratch (static device globals; no allocation) ----------------
__device__ float g_xl[N_NODES * C_OUT];       // projected features [N,128]
__device__ float g_asrc[N_NODES * HEADS];     // per-node src attention logit
__device__ float g_adst[N_NODES * HEADS];     // per-node dst attention logit
__device__ int   g_count[N_NODES];            // in-degree histogram (no self loops)
__device__ int   g_rowptr[N_NODES + 1];       // CSR row pointer (by destination)
__device__ int   g_cursor[N_NODES];           // scatter cursors
__device__ int   g_srcs[N_EDGES];             // dst-sorted source indices

__device__ __forceinline__ float leaky(float v) {
    return v > 0.0f ? v : NEG_SLOPE * v;
}

// ---------------- K1: xl = x @ W  (M=50000, N=128, K=128 fp32) ----------------
__global__ __launch_bounds__(256) void gemm128(const float* __restrict__ X,
                                               const float* __restrict__ W) {
    __shared__ float As[16][132];   // transposed A tile [k][row], padded
    __shared__ float Bs[16][128];   // B tile [k][col]
    const int tid  = threadIdx.x;
    const int row0 = blockIdx.x * 128;
    const int tx = tid & 15, ty = tid >> 4;

    float acc[8][8];
#pragma unroll
    for (int i = 0; i < 8; i++)
#pragma unroll
        for (int j = 0; j < 8; j++) acc[i][j] = 0.0f;

    const int arow = tid >> 1;          // 0..127
    const int akc  = (tid & 1) * 8;     // 0 or 8
    const int brow = tid >> 4;          // 0..15
    const int bcol = (tid & 15) * 8;    // 0..120
    const int grow = row0 + arow;
    const bool avalid = grow < N_NODES;

    for (int k0 = 0; k0 < C_IN; k0 += 16) {
        float4 a0 = make_float4(0, 0, 0, 0), a1 = make_float4(0, 0, 0, 0);
        if (avalid) {
            a0 = *(const float4*)(X + (size_t)grow * C_IN + k0 + akc);
            a1 = *(const float4*)(X + (size_t)grow * C_IN + k0 + akc + 4);
        }
        float4 b0 = *(const float4*)(W + (size_t)(k0 + brow) * C_OUT + bcol);
        float4 b1 = *(const float4*)(W + (size_t)(k0 + brow) * C_OUT + bcol + 4);
        __syncthreads();
        As[akc + 0][arow] = a0.x; As[akc + 1][arow] = a0.y;
        As[akc + 2][arow] = a0.z; As[akc + 3][arow] = a0.w;
        As[akc + 4][arow] = a1.x; As[akc + 5][arow] = a1.y;
        As[akc + 6][arow] = a1.z; As[akc + 7][arow] = a1.w;
        *(float4*)&Bs[brow][bcol]     = b0;
        *(float4*)&Bs[brow][bcol + 4] = b1;
        __syncthreads();
#pragma unroll
        for (int k = 0; k < 16; k++) {
            float a[8], b[8];
            *(float4*)(a)     = *(const float4*)&As[k][ty * 8];
            *(float4*)(a + 4) = *(const float4*)&As[k][ty * 8 + 4];
            *(float4*)(b)     = *(const float4*)&Bs[k][tx * 8];
            *(float4*)(b + 4) = *(const float4*)&Bs[k][tx * 8 + 4];
#pragma unroll
            for (int i = 0; i < 8; i++)
#pragma unroll
                for (int j = 0; j < 8; j++) acc[i][j] = fmaf(a[i], b[j], acc[i][j]);
        }
    }
#pragma unroll
    for (int i = 0; i < 8; i++) {
        int r = row0 + ty * 8 + i;
        if (r < N_NODES) {
            *(float4*)(g_xl + (size_t)r * C_OUT + tx * 8)     = make_float4(acc[i][0], acc[i][1], acc[i][2], acc[i][3]);
            *(float4*)(g_xl + (size_t)r * C_OUT + tx * 8 + 4) = make_float4(acc[i][4], acc[i][5], acc[i][6], acc[i][7]);
        }
    }
}

// ---------------- K2: per-(node,head) attention dots (+ zero histogram) ----------------
__global__ void node_attn(const float* __restrict__ att_src,
                          const float* __restrict__ att_dst) {
    int t = blockIdx.x * blockDim.x + threadIdx.x;   // n*HEADS + h
    if (t < N_NODES) g_count[t] = 0;
    if (t >= N_NODES * HEADS) return;
    int n = t >> 2, h = t & 3;
    const float4* row = (const float4*)(g_xl + (size_t)n * C_OUT + h * C_HEAD);
    const float4* as  = (const float4*)(att_src + h * C_HEAD);
    const float4* ad  = (const float4*)(att_dst + h * C_HEAD);
    float s = 0.0f, d = 0.0f;
#pragma unroll
    for (int i = 0; i < 8; i++) {
        float4 v = row[i], a = as[i], b = ad[i];
        s += v.x * a.x + v.y * a.y + v.z * a.z + v.w * a.w;
        d += v.x * b.x + v.y * b.y + v.z * b.z + v.w * b.w;
    }
    g_asrc[t] = s;
    g_adst[t] = d;
}

// ---------------- K3: in-degree histogram (self-loops dropped) ----------------
__global__ void hist(const int* __restrict__ ei) {
    int e = blockIdx.x * blockDim.x + threadIdx.x;
    if (e >= N_EDGES) return;
    int s = __ldg(ei + e);
    int d = __ldg(ei + N_EDGES + e);
    if (s == d) return;
    atomicAdd(&g_count[d], 1);
}

// ---------------- K4: exclusive scan of histogram (single block) ----------------
__global__ __launch_bounds__(1024) void scan() {
    __shared__ int ssum[1024];
    const int T = 1024;
    int t = threadIdx.x;
    const int per = (N_NODES + T - 1) / T;
    int lo = t * per;
    int hi = min(lo + per, N_NODES);
    int sum = 0;
    for (int i = lo; i < hi; i++) sum += g_count[i];
    ssum[t] = sum;
    __syncthreads();
    for (int off = 1; off < T; off <<= 1) {
        int v = (t >= off) ? ssum[t - off] : 0;
        __syncthreads();
        ssum[t] += v;
        __syncthreads();
    }
    int run = (t > 0) ? ssum[t - 1] : 0;
    for (int i = lo; i < hi; i++) {
        int c = g_count[i];
        g_rowptr[i] = run;
        g_cursor[i] = run;
        run += c;
    }
    if (t == T - 1) g_rowptr[N_NODES] = run;
}

// ---------------- K5: scatter edges into CSR buckets ----------------
__global__ void scatter(const int* __restrict__ ei) {
    int e = blockIdx.x * blockDim.x + threadIdx.x;
    if (e >= N_EDGES) return;
    int s = __ldg(ei + e);
    int d = __ldg(ei + N_EDGES + e);
    if (s == d) return;
    int pos = atomicAdd(&g_cursor[d], 1);
    g_srcs[pos] = s;
}

// ---------------- K6: warp-per-destination aggregation (atomic-free output) ----------------
__global__ __launch_bounds__(256) void aggr_csr(const float* __restrict__ bias,
                                                float* __restrict__ out) {
    int n    = (blockIdx.x * blockDim.x + threadIdx.x) >> 5;   // dst node
    int lane = threadIdx.x & 31;
    if (n >= N_NODES) return;
    int h = lane >> 3;            // head for this lane's 4 channels
    int c = lane * 4;             // channel offset in [0,128)

    float adv = g_adst[n * 4 + h];
    // self-loop term
    float w = __expf(leaky(g_asrc[n * 4 + h] + adv));
    float4 v = *(const float4*)(g_xl + (size_t)n * C_OUT + c);
    float ax = w * v.x, ay = w * v.y, az = w * v.z, aw = w * v.w;
    float dn = w;

    int start = g_rowptr[n];
    int end   = g_rowptr[n + 1];
    for (int base = start; base < end; base += 32) {
        int cnt = end - base;
        if (cnt > 32) cnt = 32;
        int sj = (lane < cnt) ? g_srcs[base + lane] : 0;
        for (int j = 0; j < cnt; j++) {
            int s = __shfl_sync(0xffffffffu, sj, j);
            float wj = __expf(leaky(g_asrc[s * 4 + h] + adv));
            float4 vj = *(const float4*)(g_xl + (size_t)s * C_OUT + c);
            ax = fmaf(wj, vj.x, ax);
            ay = fmaf(wj, vj.y, ay);
            az = fmaf(wj, vj.z, az);
            aw = fmaf(wj, vj.w, aw);
            dn += wj;
        }
    }

    float inv = 0.5f / dn;
    float4 b = *(const float4*)(bias + c);
    float4 r;
    r.x = 0.5f * b.x + inv * ax;
    r.y = 0.5f * b.y + inv * ay;
    r.z = 0.5f * b.z + inv * az;
    r.w = 0.5f * b.w + inv * aw;
    *(float4*)(out + (size_t)n * C_OUT + c) = r;
}

// ---------------- launch ----------------
extern "C" void kernel_launch(void* const* d_in, const int* in_sizes, int n_in,
                              void* d_out, int out_size) {
    const float* x   = (const float*)d_in[0];
    const int*   ei  = (const int*)d_in[1];
    const float* W   = (const float*)d_in[2];
    const float* as  = (const float*)d_in[3];
    const float* ad  = (const float*)d_in[4];
    const float* bs  = (const float*)d_in[5];
    float*       out = (float*)d_out;

    gemm128<<<(N_NODES + 127) / 128, 256>>>(x, W);
    node_attn<<<(N_NODES * HEADS + 255) / 256, 256>>>(as, ad);
    hist<<<(N_EDGES + 255) / 256, 256>>>(ei);
    scan<<<1, 1024>>>();
    scatter<<<(N_EDGES + 255) / 256, 256>>>(ei);
    aggr_csr<<<(N_NODES * 32 + 255) / 256, 256>>>(bs, out);
}

// round 5
// speedup vs baseline: 1.5482x; 1.5482x over previous
#include <cuda_runtime.h>

#define N_NODES 50000
#define N_EDGES 800000
#define C_IN    128
#define HEADS   4
#define C_HEAD  32
#define C_OUT   128
#define NEG_SLOPE 0.2f

#define SCAN_T 512
#define SCAN_B ((N_NODES + SCAN_T - 1) / SCAN_T)   // 98

// ---------------- scratch (static device globals; no allocation) ----------------
__device__ float g_xl[N_NODES * C_OUT];       // projected features [N,128]
__device__ float g_asrc[N_NODES * HEADS];     // per-node src attention logit
__device__ float g_adst[N_NODES * HEADS];     // per-node dst attention logit
__device__ int   g_count[N_NODES];            // in-degree histogram (no self loops)
__device__ int   g_rowptr[N_NODES + 1];       // CSR row pointer (by destination)
__device__ int   g_cursor[N_NODES];           // scatter cursors
__device__ int   g_srcs[N_EDGES];             // dst-sorted source indices
__device__ int   g_bsum[SCAN_B];              // per-block scan partials

__device__ __forceinline__ float leaky(float v) {
    return v > 0.0f ? v : NEG_SLOPE * v;
}

// ---------------- K1: xl = x @ W  (M=50000, N=128, K=128 fp32) ----------------
__global__ __launch_bounds__(256) void gemm128(const float* __restrict__ X,
                                               const float* __restrict__ W) {
    __shared__ float As[16][132];   // transposed A tile [k][row], padded
    __shared__ float Bs[16][128];   // B tile [k][col]
    const int tid  = threadIdx.x;
    const int row0 = blockIdx.x * 128;
    const int tx = tid & 15, ty = tid >> 4;

    float acc[8][8];
#pragma unroll
    for (int i = 0; i < 8; i++)
#pragma unroll
        for (int j = 0; j < 8; j++) acc[i][j] = 0.0f;

    const int arow = tid >> 1;          // 0..127
    const int akc  = (tid & 1) * 8;     // 0 or 8
    const int brow = tid >> 4;          // 0..15
    const int bcol = (tid & 15) * 8;    // 0..120
    const int grow = row0 + arow;
    const bool avalid = grow < N_NODES;

    for (int k0 = 0; k0 < C_IN; k0 += 16) {
        float4 a0 = make_float4(0, 0, 0, 0), a1 = make_float4(0, 0, 0, 0);
        if (avalid) {
            a0 = *(const float4*)(X + (size_t)grow * C_IN + k0 + akc);
            a1 = *(const float4*)(X + (size_t)grow * C_IN + k0 + akc + 4);
        }
        float4 b0 = *(const float4*)(W + (size_t)(k0 + brow) * C_OUT + bcol);
        float4 b1 = *(const float4*)(W + (size_t)(k0 + brow) * C_OUT + bcol + 4);
        __syncthreads();
        As[akc + 0][arow] = a0.x; As[akc + 1][arow] = a0.y;
        As[akc + 2][arow] = a0.z; As[akc + 3][arow] = a0.w;
        As[akc + 4][arow] = a1.x; As[akc + 5][arow] = a1.y;
        As[akc + 6][arow] = a1.z; As[akc + 7][arow] = a1.w;
        *(float4*)&Bs[brow][bcol]     = b0;
        *(float4*)&Bs[brow][bcol + 4] = b1;
        __syncthreads();
#pragma unroll
        for (int k = 0; k < 16; k++) {
            float a[8], b[8];
            *(float4*)(a)     = *(const float4*)&As[k][ty * 8];
            *(float4*)(a + 4) = *(const float4*)&As[k][ty * 8 + 4];
            *(float4*)(b)     = *(const float4*)&Bs[k][tx * 8];
            *(float4*)(b + 4) = *(const float4*)&Bs[k][tx * 8 + 4];
#pragma unroll
            for (int i = 0; i < 8; i++)
#pragma unroll
                for (int j = 0; j < 8; j++) acc[i][j] = fmaf(a[i], b[j], acc[i][j]);
        }
    }
#pragma unroll
    for (int i = 0; i < 8; i++) {
        int r = row0 + ty * 8 + i;
        if (r < N_NODES) {
            *(float4*)(g_xl + (size_t)r * C_OUT + tx * 8)     = make_float4(acc[i][0], acc[i][1], acc[i][2], acc[i][3]);
            *(float4*)(g_xl + (size_t)r * C_OUT + tx * 8 + 4) = make_float4(acc[i][4], acc[i][5], acc[i][6], acc[i][7]);
        }
    }
}

// ---------------- K2: per-(node,head) attention dots (+ zero histogram) ----------------
__global__ void node_attn(const float* __restrict__ att_src,
                          const float* __restrict__ att_dst) {
    int t = blockIdx.x * blockDim.x + threadIdx.x;   // n*HEADS + h
    if (t < N_NODES) g_count[t] = 0;
    if (t >= N_NODES * HEADS) return;
    int n = t >> 2, h = t & 3;
    const float4* row = (const float4*)(g_xl + (size_t)n * C_OUT + h * C_HEAD);
    const float4* as  = (const float4*)(att_src + h * C_HEAD);
    const float4* ad  = (const float4*)(att_dst + h * C_HEAD);
    float s = 0.0f, d = 0.0f;
#pragma unroll
    for (int i = 0; i < 8; i++) {
        float4 v = row[i], a = as[i], b = ad[i];
        s += v.x * a.x + v.y * a.y + v.z * a.z + v.w * a.w;
        d += v.x * b.x + v.y * b.y + v.z * b.z + v.w * b.w;
    }
    g_asrc[t] = s;
    g_adst[t] = d;
}

// ---------------- K3: in-degree histogram (self-loops dropped) ----------------
__global__ void hist(const int* __restrict__ ei) {
    int e = blockIdx.x * blockDim.x + threadIdx.x;
    if (e >= N_EDGES) return;
    int s = __ldg(ei + e);
    int d = __ldg(ei + N_EDGES + e);
    if (s == d) return;
    atomicAdd(&g_count[d], 1);
}

// ---------------- K4a: per-block exclusive scan ----------------
__global__ __launch_bounds__(SCAN_T) void scan_local() {
    int tid  = threadIdx.x;
    int i    = blockIdx.x * SCAN_T + tid;
    int lane = tid & 31, wid = tid >> 5;
    int v = (i < N_NODES) ? g_count[i] : 0;

    // inclusive warp scan
    int x = v;
#pragma unroll
    for (int off = 1; off < 32; off <<= 1) {
        int t = __shfl_up_sync(0xffffffffu, x, off);
        if (lane >= off) x += t;
    }
    __shared__ int wsum[SCAN_T / 32];
    if (lane == 31) wsum[wid] = x;
    __syncthreads();
    if (wid == 0) {
        int y = (lane < SCAN_T / 32) ? wsum[lane] : 0;
#pragma unroll
        for (int off = 1; off < 32; off <<= 1) {
            int t = __shfl_up_sync(0xffffffffu, y, off);
            if (lane >= off) y += t;
        }
        if (lane < SCAN_T / 32) wsum[lane] = y;
    }
    __syncthreads();
    int excl = x - v + (wid > 0 ? wsum[wid - 1] : 0);
    if (i < N_NODES) g_rowptr[i] = excl;           // pre-offset local scan
    if (tid == SCAN_T - 1) g_bsum[blockIdx.x] = excl + v;   // block total
}

// ---------------- K4b: scan the block sums (1 small block) ----------------
__global__ __launch_bounds__(128) void scan_sums() {
    int tid  = threadIdx.x;
    int lane = tid & 31, wid = tid >> 5;
    int v = (tid < SCAN_B) ? g_bsum[tid] : 0;
    int x = v;
#pragma unroll
    for (int off = 1; off < 32; off <<= 1) {
        int t = __shfl_up_sync(0xffffffffu, x, off);
        if (lane >= off) x += t;
    }
    __shared__ int wsum[4];
    if (lane == 31) wsum[wid] = x;
    __syncthreads();
    if (wid == 0) {
        int y = (lane < 4) ? wsum[lane] : 0;
#pragma unroll
        for (int off = 1; off < 4; off <<= 1) {
            int t = __shfl_up_sync(0xffffffffu, y, off);
            if (lane >= off) y += t;
        }
        if (lane < 4) wsum[lane] = y;
    }
    __syncthreads();
    int incl = x + (wid > 0 ? wsum[wid - 1] : 0);
    if (tid < SCAN_B) g_bsum[tid] = incl - v;      // exclusive offsets
    if (tid == 127) g_rowptr[N_NODES] = incl;      // grand total (last inclusive)
}

// ---------------- K4c: add block offsets, write rowptr + cursor ----------------
__global__ __launch_bounds__(SCAN_T) void scan_add() {
    int i = blockIdx.x * SCAN_T + threadIdx.x;
    if (i >= N_NODES) return;
    int r = g_rowptr[i] + g_bsum[blockIdx.x];
    g_rowptr[i] = r;
    g_cursor[i] = r;
}

// ---------------- K5: scatter edges into CSR buckets ----------------
__global__ void scatter(const int* __restrict__ ei) {
    int e = blockIdx.x * blockDim.x + threadIdx.x;
    if (e >= N_EDGES) return;
    int s = __ldg(ei + e);
    int d = __ldg(ei + N_EDGES + e);
    if (s == d) return;
    int pos = atomicAdd(&g_cursor[d], 1);
    g_srcs[pos] = s;
}

// ---------------- K6: warp-per-destination aggregation (atomic-free output) ----------------
__global__ __launch_bounds__(256) void aggr_csr(const float* __restrict__ bias,
                                                float* __restrict__ out) {
    int n    = (blockIdx.x * blockDim.x + threadIdx.x) >> 5;   // dst node
    int lane = threadIdx.x & 31;
    if (n >= N_NODES) return;
    int h = lane >> 3;            // head for this lane's 4 channels
    int c = lane * 4;             // channel offset in [0,128)

    float adv = g_adst[n * 4 + h];
    // self-loop term
    float w = __expf(leaky(g_asrc[n * 4 + h] + adv));
    float4 v = *(const float4*)(g_xl + (size_t)n * C_OUT + c);
    float ax = w * v.x, ay = w * v.y, az = w * v.z, aw = w * v.w;
    float dn = w;

    int start = g_rowptr[n];
    int end   = g_rowptr[n + 1];
    for (int base = start; base < end; base += 32) {
        int cnt = end - base;
        if (cnt > 32) cnt = 32;
        int sj = (lane < cnt) ? g_srcs[base + lane] : 0;
        for (int j = 0; j < cnt; j++) {
            int s = __shfl_sync(0xffffffffu, sj, j);
            float wj = __expf(leaky(g_asrc[s * 4 + h] + adv));
            float4 vj = *(const float4*)(g_xl + (size_t)s * C_OUT + c);
            ax = fmaf(wj, vj.x, ax);
            ay = fmaf(wj, vj.y, ay);
            az = fmaf(wj, vj.z, az);
            aw = fmaf(wj, vj.w, aw);
            dn += wj;
        }
    }

    float inv = 0.5f / dn;
    float4 b = *(const float4*)(bias + c);
    float4 r;
    r.x = 0.5f * b.x + inv * ax;
    r.y = 0.5f * b.y + inv * ay;
    r.z = 0.5f * b.z + inv * az;
    r.w = 0.5f * b.w + inv * aw;
    *(float4*)(out + (size_t)n * C_OUT + c) = r;
}

// ---------------- launch ----------------
extern "C" void kernel_launch(void* const* d_in, const int* in_sizes, int n_in,
                              void* d_out, int out_size) {
    const float* x   = (const float*)d_in[0];
    const int*   ei  = (const int*)d_in[1];
    const float* W   = (const float*)d_in[2];
    const float* as  = (const float*)d_in[3];
    const float* ad  = (const float*)d_in[4];
    const float* bs  = (const float*)d_in[5];
    float*       out = (float*)d_out;

    gemm128<<<(N_NODES + 127) / 128, 256>>>(x, W);
    node_attn<<<(N_NODES * HEADS + 255) / 256, 256>>>(as, ad);
    hist<<<(N_EDGES + 255) / 256, 256>>>(ei);
    scan_local<<<SCAN_B, SCAN_T>>>();
    scan_sums<<<1, 128>>>();
    scan_add<<<SCAN_B, SCAN_T>>>();
    scatter<<<(N_EDGES + 255) / 256, 256>>>(ei);
    aggr_csr<<<(N_NODES * 32 + 255) / 256, 256>>>(bs, out);
}